// round 7
// baseline (speedup 1.0000x reference)
#include <cuda_runtime.h>

// H_13048110646034 v7: 2 warps share one p + one cp.async weight ring.
// CTA = 64 thr: warp = batch-half (b = warp*4+0..3); lane = (og 0..15, cout).
// Each lane owns output quad og of cout for 4 batches -> 16 accum floats.
// Weight ring: 2 bufs x (4 mats x 4 i-rows x 64) = 8 KB; x tile 4 KB.
// 12 KB smem + ~56 regs -> 2048 CTAs all co-resident (36 warps/SM).
// Each CTA processes p and p+2048; seam prefetch keeps cp.async stream full.

#define B_  8
#define N_  16384
#define P_  4096

__device__ __forceinline__ void cp_async16(void* smem_dst, const void* gsrc) {
    unsigned saddr = (unsigned)__cvta_generic_to_shared(smem_dst);
    asm volatile("cp.async.cg.shared.global [%0], [%1], 16;\n" :: "r"(saddr), "l"(gsrc));
}
__device__ __forceinline__ void cp_commit() { asm volatile("cp.async.commit_group;\n"); }
template <int N>
__device__ __forceinline__ void cp_wait() {
    asm volatile("cp.async.wait_group %0;\n" :: "n"(N));
}

__global__ __launch_bounds__(64, 16)
void butterfly_local_v7(const float* __restrict__ x,
                        const float* __restrict__ Wrr,
                        const float* __restrict__ Wri,
                        const float* __restrict__ Wir,
                        const float* __restrict__ Wii,
                        const int*   __restrict__ perm,
                        float* __restrict__ out)
{
    const int tid  = threadIdx.x;            // 0..63
    const int wrp  = tid >> 5;               // batch half 0..1
    const int lane = tid & 31;
    const int p0   = blockIdx.x;
    const int p1   = p0 + 2048;

    __shared__ float Wsm[2][4][4][64];       // [buf][mat][i_local][o] = 8 KB
    __shared__ float xsm[64][16];            // [i][b*2+c]             = 4 KB

    const float* const Wm[4] = { Wrr, Wri, Wir, Wii };
    const size_t pq[2] = { (size_t)p0 * 1024, (size_t)p1 * 1024 };

    // chunk CC = i in [CC*4, CC*4+4): 256 float4 (4 mats x 64), 4 per thread
    #define FILL_CHUNK(PQ, CC, BUF)                                           \
        {                                                                     \
            const size_t _pq = (PQ);                                          \
            const int _c = (CC);                                              \
            _Pragma("unroll")                                                 \
            for (int k = 0; k < 4; k++) {                                     \
                const int r   = k * 64 + tid;      /* 0..255 */               \
                const int mat = r >> 6;                                       \
                const int rem = r & 63;                                       \
                cp_async16(((float4*)&Wsm[BUF][0][0][0]) + r,                 \
                           ((const float4*)Wm[mat]) + _pq + _c * 64 + rem);   \
            }                                                                 \
            cp_commit();                                                      \
        }

    // gather x for block P: 256 float4, 4 per thread; cb = tid&15 spreads banks
    #define GATHER_X(P)                                                       \
        {                                                                     \
            const int _p = (P);                                               \
            const int cb = tid & 15;                                          \
            _Pragma("unroll")                                                 \
            for (int it = 0; it < 4; it++) {                                  \
                const int jf = (tid >> 4) + it * 4;  /* 0..15 */              \
                const int j  = jf >> 2;                                       \
                const int f4 = jf & 3;                                        \
                const int n  = __ldg(&perm[_p * 4 + j]);                      \
                const float4 v = *(const float4*)&x[(((size_t)cb * N_) + n) * 16 + f4 * 4]; \
                const int i0 = j * 16 + f4 * 4;                               \
                xsm[i0 + 0][cb] = v.x;                                        \
                xsm[i0 + 1][cb] = v.y;                                        \
                xsm[i0 + 2][cb] = v.z;                                        \
                xsm[i0 + 3][cb] = v.w;                                        \
            }                                                                 \
        }

    FILL_CHUNK(pq[0], 0, 0);
    FILL_CHUNK(pq[0], 1, 1);
    GATHER_X(p0);

    const int og   = lane & 15;              // output quad 0..15
    const int cout = lane >> 4;              // 0 = re, 1 = im
    const int matA = cout * 2;               // rr or ir
    const int matB = cout * 2 + 1;           // ri or ii

    for (int rep = 0; rep < 2; rep++) {
        const int p = rep ? p1 : p0;

        if (rep) {                            // p1 weights already in flight
            __syncthreads();                  // everyone done reading p0's xsm
            GATHER_X(p1);
        }

        float4 acc[4];
        #pragma unroll
        for (int k = 0; k < 4; k++) acc[k] = make_float4(0.f, 0.f, 0.f, 0.f);

        for (int c = 0; c < 16; c++) {
            cp_wait<1>();
            __syncthreads();                  // buf ready + xsm visible
            const int buf = c & 1;

            #pragma unroll
            for (int ii = 0; ii < 4; ii++) {
                const int i = c * 4 + ii;
                const float4 xa = *(const float4*)&xsm[i][wrp * 8];
                const float4 xb = *(const float4*)&xsm[i][wrp * 8 + 4];
                const float4 wA = *(const float4*)&Wsm[buf][matA][ii][og * 4];
                const float4 wB = *(const float4*)&Wsm[buf][matB][ii][og * 4];

                const float xr[4] = { xa.x, xa.z, xb.x, xb.z };
                const float xi[4] = { xa.y, xa.w, xb.y, xb.w };

                #pragma unroll
                for (int k = 0; k < 4; k++) {
                    acc[k].x = fmaf(xr[k], wA.x, acc[k].x); acc[k].x = fmaf(xi[k], wB.x, acc[k].x);
                    acc[k].y = fmaf(xr[k], wA.y, acc[k].y); acc[k].y = fmaf(xi[k], wB.y, acc[k].y);
                    acc[k].z = fmaf(xr[k], wA.z, acc[k].z); acc[k].z = fmaf(xi[k], wB.z, acc[k].z);
                    acc[k].w = fmaf(xr[k], wA.w, acc[k].w); acc[k].w = fmaf(xi[k], wB.w, acc[k].w);
                }
            }

            __syncthreads();                  // both warps done reading buf
            const int g = rep * 16 + c + 2;   // next global chunk
            if (g < 32) {
                FILL_CHUNK(pq[g >> 4], g & 15, buf);
            } else {
                cp_commit();                  // keep group accounting uniform
            }
        }

        // store: out[b, cout, 4p..4p+3, :] contiguous 64-float run per (b,cout)
        #pragma unroll
        for (int k = 0; k < 4; k++) {
            const int b = wrp * 4 + k;
            const size_t off = (((size_t)(b * 2 + cout) * N_) + 4 * (size_t)p) * 16 + og * 4;
            *(float4*)&out[off] = acc[k];
        }
    }
    #undef FILL_CHUNK
    #undef GATHER_X
}

extern "C" void kernel_launch(void* const* d_in, const int* in_sizes, int n_in,
                              void* d_out, int out_size)
{
    const float* x    = (const float*)d_in[0];
    const float* Wrr  = (const float*)d_in[1];
    const float* Wri  = (const float*)d_in[2];
    const float* Wir  = (const float*)d_in[3];
    const float* Wii  = (const float*)d_in[4];
    const int*   perm = (const int*)d_in[5];
    float* out = (float*)d_out;

    butterfly_local_v7<<<P_ / 2, 64>>>(x, Wrr, Wri, Wir, Wii, perm, out);
}

// round 8
// speedup vs baseline: 1.1047x; 1.1047x over previous
#include <cuda_runtime.h>

// H_13048110646034 v8 = v5 layout + packed f32x2 FMA (FFMA2).
// One warp per p; cp.async weight ring (2 bufs x 4 i-rows x 4 mats, 8 KB/warp).
// Lane = (oslot 0..7, bslot, cout) owns o-quads {oslot, oslot+8} x 4 batches.
// Math per i: 32 FFMA2 + 8 packs (was 64 FFMA) -> ~35% fewer instructions on an
// issue-bound kernel.

#define B_  8
#define N_  16384
#define P_  4096

__device__ __forceinline__ void cp_async16(void* smem_dst, const void* gsrc) {
    unsigned saddr = (unsigned)__cvta_generic_to_shared(smem_dst);
    asm volatile("cp.async.cg.shared.global [%0], [%1], 16;\n" :: "r"(saddr), "l"(gsrc));
}
__device__ __forceinline__ void cp_commit() { asm volatile("cp.async.commit_group;\n"); }
template <int N>
__device__ __forceinline__ void cp_wait() {
    asm volatile("cp.async.wait_group %0;\n" :: "n"(N));
}

// d = a*b + d, two packed fp32 lanes (FFMA2; PTX-only, never emitted by ptxas)
__device__ __forceinline__ void ffma2(unsigned long long& d,
                                      unsigned long long a,
                                      unsigned long long b) {
    asm("fma.rn.f32x2 %0, %1, %2, %0;" : "+l"(d) : "l"(a), "l"(b));
}
// duplicate a scalar float into both lanes of an f32x2
__device__ __forceinline__ unsigned long long dup2(float x) {
    unsigned long long r;
    unsigned u = __float_as_uint(x);
    asm("mov.b64 %0, {%1, %1};" : "=l"(r) : "r"(u));
    return r;
}

__global__ __launch_bounds__(64, 9)
void butterfly_local_v8(const float* __restrict__ x,
                        const float* __restrict__ Wrr,
                        const float* __restrict__ Wri,
                        const float* __restrict__ Wir,
                        const float* __restrict__ Wii,
                        const int*   __restrict__ perm,
                        float* __restrict__ out)
{
    const int w    = threadIdx.x >> 5;       // warp 0..1, one p each
    const int lane = threadIdx.x & 31;
    const int p    = blockIdx.x * 2 + w;

    // Weights: [warp][buf][mat][i_local 4][o 64] = 16 KB total (8 KB/warp)
    __shared__ float Wsm[2][2][4][4][64];
    // x: [warp][i 64][cb 16] = 8 KB
    __shared__ float xsm[2][64][16];

    const float* const Wm[4] = { Wrr, Wri, Wir, Wii };
    const size_t pq = (size_t)p * 1024;      // float4 units per mat per p

    #define FILL_CHUNK(CC, BUF)                                               \
        {                                                                     \
            const int _c = (CC);                                              \
            _Pragma("unroll")                                                 \
            for (int k = 0; k < 8; k++) {                                     \
                const int mat = k >> 1;                                       \
                const int rem = (k & 1) * 32 + lane;                          \
                cp_async16(((float4*)&Wsm[w][BUF][mat][0][0]) + rem,          \
                           ((const float4*)Wm[mat]) + pq + _c * 64 + rem);    \
            }                                                                 \
            cp_commit();                                                      \
        }

    FILL_CHUNK(0, 0);
    FILL_CHUNK(1, 1);

    // ---- x gather (cb = lane&15 spreads STS banks) ----
    {
        const int cb = lane & 15;
        const int hi = lane >> 4;
        #pragma unroll
        for (int it = 0; it < 8; it++) {
            const int jf = it * 2 + hi;      // 0..15
            const int j  = jf >> 2;
            const int f4 = jf & 3;
            const int n  = __ldg(&perm[p * 4 + j]);
            const float4 v = *(const float4*)&x[(((size_t)cb * N_) + n) * 16 + f4 * 4];
            const int i0 = j * 16 + f4 * 4;
            xsm[w][i0 + 0][cb] = v.x;
            xsm[w][i0 + 1][cb] = v.y;
            xsm[w][i0 + 2][cb] = v.z;
            xsm[w][i0 + 3][cb] = v.w;
        }
    }
    __syncwarp();

    const int oslot = lane & 7;              // o-quads oslot and oslot+8
    const int bslot = (lane >> 3) & 1;       // b = bslot*4 + 0..3
    const int cout  = lane >> 4;             // 0 = re, 1 = im
    const int matA  = cout * 2;
    const int matB  = cout * 2 + 1;

    // packed accumulators: quad oslot = (aL0,aL1), quad oslot+8 = (aH0,aH1)
    unsigned long long aL0[4], aL1[4], aH0[4], aH1[4];
    #pragma unroll
    for (int k = 0; k < 4; k++) { aL0[k] = 0ull; aL1[k] = 0ull; aH0[k] = 0ull; aH1[k] = 0ull; }

    for (int c = 0; c < 16; c++) {
        cp_wait<1>();
        __syncwarp();
        const int buf = c & 1;

        #pragma unroll
        for (int ii = 0; ii < 4; ii++) {
            const int i = c * 4 + ii;
            const float4 xa = *(const float4*)&xsm[w][i][bslot * 8];
            const float4 xb = *(const float4*)&xsm[w][i][bslot * 8 + 4];

            const unsigned long long xr[4] = { dup2(xa.x), dup2(xa.z), dup2(xb.x), dup2(xb.z) };
            const unsigned long long xi[4] = { dup2(xa.y), dup2(xa.w), dup2(xb.y), dup2(xb.w) };

            const ulonglong2 wA0 = *(const ulonglong2*)&Wsm[w][buf][matA][ii][oslot * 4];
            const ulonglong2 wA1 = *(const ulonglong2*)&Wsm[w][buf][matA][ii][32 + oslot * 4];
            const ulonglong2 wB0 = *(const ulonglong2*)&Wsm[w][buf][matB][ii][oslot * 4];
            const ulonglong2 wB1 = *(const ulonglong2*)&Wsm[w][buf][matB][ii][32 + oslot * 4];

            #pragma unroll
            for (int k = 0; k < 4; k++) {
                ffma2(aL0[k], xr[k], wA0.x); ffma2(aL1[k], xr[k], wA0.y);
                ffma2(aL0[k], xi[k], wB0.x); ffma2(aL1[k], xi[k], wB0.y);
                ffma2(aH0[k], xr[k], wA1.x); ffma2(aH1[k], xr[k], wA1.y);
                ffma2(aH0[k], xi[k], wB1.x); ffma2(aH1[k], xi[k], wB1.y);
            }
        }

        __syncwarp();                        // all lanes done reading buf
        if (c < 14) {
            FILL_CHUNK(c + 2, buf);
        } else {
            cp_commit();                     // keep group accounting uniform
        }
    }

    // ---- store: out[b, cout, 4p..4p+3, :] contiguous 64-float run ----
    #pragma unroll
    for (int k = 0; k < 4; k++) {
        const int b = bslot * 4 + k;
        const size_t off = (((size_t)(b * 2 + cout) * N_) + 4 * (size_t)p) * 16;
        ulonglong2 lo; lo.x = aL0[k]; lo.y = aL1[k];
        ulonglong2 hi; hi.x = aH0[k]; hi.y = aH1[k];
        *(ulonglong2*)&out[off + oslot * 4]      = lo;
        *(ulonglong2*)&out[off + 32 + oslot * 4] = hi;
    }
    #undef FILL_CHUNK
}

extern "C" void kernel_launch(void* const* d_in, const int* in_sizes, int n_in,
                              void* d_out, int out_size)
{
    const float* x    = (const float*)d_in[0];
    const float* Wrr  = (const float*)d_in[1];
    const float* Wri  = (const float*)d_in[2];
    const float* Wir  = (const float*)d_in[3];
    const float* Wii  = (const float*)d_in[4];
    const int*   perm = (const int*)d_in[5];
    float* out = (float*)d_out;

    butterfly_local_v8<<<P_ / 2, 64>>>(x, Wrr, Wri, Wir, Wii, perm, out);
}